// round 6
// baseline (speedup 1.0000x reference)
#include <cuda_runtime.h>
#include <cuda_fp16.h>
#include <cstdint>

// Problem constants
#define NROWS   500000
#define KCODES  512
#define DDIM    64
#define TILE_M  512
#define NTHREADS 512
#define NUMTILES ((NROWS + TILE_M - 1) / TILE_M)   // 977

// Shared memory layout (byte offsets into dynamic smem)
#define SMEM_B_HI   0            // 512 x 128B fp16 (-2*e hi), SW128-swizzled
#define SMEM_B_LO   65536        // 512 x 128B fp16 (-2*e residual)
#define SMEM_ESQ    131072       // 512 floats (||e_k||^2)
#define SMEM_IDX    133120       // 512 int2 (top-2 candidates per row)
#define SMEM_WIN    137216       // 512 int  (winner per row)
#define SMEM_TOTAL  139264

__device__ __forceinline__ uint32_t smem_u32(const void* p) {
    uint32_t a;
    asm("{ .reg .u64 t; cvta.to.shared.u64 t, %1; cvt.u32.u64 %0, t; }" : "=r"(a) : "l"(p));
    return a;
}
__device__ __forceinline__ uint32_t swz(uint32_t bo) { return bo ^ ((bo >> 3) & 0x70); }

__device__ __forceinline__ void mma_f16(float* d, const uint32_t* a, const uint32_t* b) {
    asm volatile(
        "mma.sync.aligned.m16n8k16.row.col.f32.f16.f16.f32 "
        "{%0,%1,%2,%3}, {%4,%5,%6,%7}, {%8,%9}, {%0,%1,%2,%3};"
        : "+f"(d[0]), "+f"(d[1]), "+f"(d[2]), "+f"(d[3])
        : "r"(a[0]), "r"(a[1]), "r"(a[2]), "r"(a[3]), "r"(b[0]), "r"(b[1]));
}
__device__ __forceinline__ void ldsm4(uint32_t* r, uint32_t addr) {
    asm volatile("ldmatrix.sync.aligned.m8n8.x4.shared.b16 {%0,%1,%2,%3}, [%4];"
        : "=r"(r[0]), "=r"(r[1]), "=r"(r[2]), "=r"(r[3]) : "r"(addr));
}

// Split float2 into fp16 hi pair + fp16 residual pair (packed).
__device__ __forceinline__ void split2(float2 v, uint32_t& h, uint32_t& l) {
    __half2 hh = __floats2half2_rn(v.x, v.y);
    float2 hf = __half22float2(hh);
    __half2 ll = __floats2half2_rn(v.x - hf.x, v.y - hf.y);
    h = *reinterpret_cast<uint32_t*>(&hh);
    l = *reinterpret_cast<uint32_t*>(&ll);
}

// Split 8 fp32 (scaled) -> fp16 hi/lo packed uint4; accumulate squares of originals.
__device__ __forceinline__ void split8(float4 v0, float4 v1, float scale,
                                       uint4& hi, uint4& lo, float& acc) {
    float f[8] = {v0.x, v0.y, v0.z, v0.w, v1.x, v1.y, v1.z, v1.w};
    uint32_t h[4], l[4];
#pragma unroll
    for (int i = 0; i < 4; i++) {
        acc = fmaf(f[2*i], f[2*i], acc);
        acc = fmaf(f[2*i+1], f[2*i+1], acc);
        split2(make_float2(f[2*i] * scale, f[2*i+1] * scale), h[i], l[i]);
    }
    hi = make_uint4(h[0], h[1], h[2], h[3]);
    lo = make_uint4(l[0], l[1], l[2], l[3]);
}

__global__ void __launch_bounds__(NTHREADS, 1) vq_kernel(
    const float* __restrict__ x, const float* __restrict__ emb,
    float* __restrict__ out, int out_size)
{
    extern __shared__ char smem[];
    const uint32_t sb = smem_u32(smem);
    const int tid  = threadIdx.x;
    const int lane = tid & 31;
    const int warpRow = (tid >> 5) * 32;     // 16 warps x 32 rows = 512 rows

    // ---- Stage B = fp16 split of (-2 * embedding), SW128; compute e_sq ----
    {
        int r = tid;                          // 0..511
        const float4* src = (const float4*)(emb + (size_t)r * DDIM);
        float ssum = 0.f;
#pragma unroll
        for (int j = 0; j < 16; j += 2) {
            uint4 hi, lo;
            split8(src[j], src[j + 1], -2.0f, hi, lo, ssum);
            uint32_t sw = swz((uint32_t)r * 128u + (uint32_t)(j >> 1) * 16u);
            *(uint4*)(smem + SMEM_B_HI + sw) = hi;
            *(uint4*)(smem + SMEM_B_LO + sw) = lo;
        }
        ((float*)(smem + SMEM_ESQ))[r] = ssum;
    }
    __syncthreads();

    // ---- Per-lane constant B addressing (swizzle algebra hoisted) ----
    const int bRow4 = (lane & 7) + ((lane >> 4) << 3);
    const int bKb4  = ((lane >> 3) & 1) << 4;
    const uint32_t laneBaseB = (uint32_t)bRow4 * 128u + (uint32_t)(bKb4 ^ ((lane & 1) << 4));
    const uint32_t kXor = (uint32_t)(lane & 6) << 4;
    uint32_t bAddrHi[4];
#pragma unroll
    for (int ks = 0; ks < 4; ks++) {
        bAddrHi[ks] = sb + SMEM_B_HI + laneBaseB + (((uint32_t)ks * 32u) ^ kXor);
    }

    const float* esq = (const float*)(smem + SMEM_ESQ);
    const int ciB = (lane & 3) * 2;

    for (int t = blockIdx.x; t < NUMTILES; t += gridDim.x) {
        const size_t base = (size_t)t * TILE_M;

        // ---- Preload B fragments for np=0, ks=0 (latency hidden by A loads) ----
        uint32_t bh[2][4], bl[2][4];
        ldsm4(bh[0], bAddrHi[0]);
        ldsm4(bl[0], bAddrHi[0] + 65536u);

        // ---- A fragments straight from global (no smem): 2 subtiles x 4 ks ----
        uint32_t ah[2][4][4], al[2][4][4];
        {
            const int kA = (lane & 3) * 2;
#pragma unroll
            for (int s = 0; s < 2; s++) {
                size_t r0 = base + warpRow + s * 16 + (lane >> 2);
                size_t r1 = r0 + 8;
                if (r0 >= NROWS) r0 = NROWS - 1;   // clamp: garbage rows never emitted
                if (r1 >= NROWS) r1 = NROWS - 1;
                const float* p0 = x + r0 * DDIM + kA;
                const float* p1 = x + r1 * DDIM + kA;
#pragma unroll
                for (int ks = 0; ks < 4; ks++) {
                    split2(*(const float2*)(p0 + ks * 16),     ah[s][ks][0], al[s][ks][0]);
                    split2(*(const float2*)(p1 + ks * 16),     ah[s][ks][1], al[s][ks][1]);
                    split2(*(const float2*)(p0 + ks * 16 + 8), ah[s][ks][2], al[s][ks][2]);
                    split2(*(const float2*)(p1 + ks * 16 + 8), ah[s][ks][3], al[s][ks][3]);
                }
            }
        }

        // ---- Top-2 trackers: tk = s*2 + rowhalf -> rows +0,+8,+16,+24 ----
        float b1[4], b2[4]; int i1[4], i2[4];
#pragma unroll
        for (int k = 0; k < 4; k++) { b1[k] = 3.4e38f; b2[k] = 3.4e38f; i1[k] = 0; i2[k] = 0; }

        uint32_t nbOff = 0;
        int nbBase = ciB;    // nb + ciB, incremented by 16 per np

#pragma unroll 1
        for (int np = 0; np < 32; np++) {
            const int nb = np * 16;
            const uint32_t nbOffN = (np == 31) ? 0u : nbOff + 2048u;
            float2 e01 = *(const float2*)(esq + nb + ciB);
            float2 e23 = *(const float2*)(esq + nb + 8 + ciB);
            float acc[2][2][4];
#pragma unroll
            for (int s = 0; s < 2; s++) {
                acc[s][0][0] = e01.x; acc[s][0][1] = e01.y;
                acc[s][0][2] = e01.x; acc[s][0][3] = e01.y;
                acc[s][1][0] = e23.x; acc[s][1][1] = e23.y;
                acc[s][1][2] = e23.x; acc[s][1][3] = e23.y;
            }

#pragma unroll
            for (int ks = 0; ks < 4; ks++) {
                const int cur = ks & 1, nxt = cur ^ 1;
                // Prefetch next ks (or next np's ks=0) while this ks's MMAs issue.
                const uint32_t pa = (ks < 3) ? (bAddrHi[ks + 1] + nbOff)
                                             : (bAddrHi[0] + nbOffN);
                ldsm4(bh[nxt], pa);
                ldsm4(bl[nxt], pa + 65536u);
                // 12 MMAs, interleaved across the 4 accumulators (dep distance 4)
                mma_f16(acc[0][0], ah[0][ks], bh[cur]);
                mma_f16(acc[0][1], ah[0][ks], bh[cur] + 2);
                mma_f16(acc[1][0], ah[1][ks], bh[cur]);
                mma_f16(acc[1][1], ah[1][ks], bh[cur] + 2);
                mma_f16(acc[0][0], al[0][ks], bh[cur]);
                mma_f16(acc[0][1], al[0][ks], bh[cur] + 2);
                mma_f16(acc[1][0], al[1][ks], bh[cur]);
                mma_f16(acc[1][1], al[1][ks], bh[cur] + 2);
                mma_f16(acc[0][0], ah[0][ks], bl[cur]);
                mma_f16(acc[0][1], ah[0][ks], bl[cur] + 2);
                mma_f16(acc[1][0], ah[1][ks], bl[cur]);
                mma_f16(acc[1][1], ah[1][ks], bl[cur] + 2);
                // lo x lo dropped: ~1e-7 per product with fp16 split; rescored exactly
            }

            // ---- Epilogue: pre-min tree (off-chain) then ONE top-2 update per tk ----
            // Next np's first LDSM is already in flight -> overlaps this block.
#pragma unroll
            for (int s = 0; s < 2; s++) {
#pragma unroll
                for (int h = 0; h < 2; h++) {
                    const int tk = s * 2 + h;
                    float s00 = acc[s][0][h*2], s01 = acc[s][0][h*2+1];
                    float s10 = acc[s][1][h*2], s11 = acc[s][1][h*2+1];
                    float m0 = fminf(s00, s01); int o0 = (s01 < s00) ? 1 : 0;
                    float m1 = fminf(s10, s11); int o1 = (s11 < s10) ? 9 : 8;
                    float m  = fminf(m0, m1);   int off = (m1 < m0) ? o1 : o0;
                    int ci = nbBase + off;
                    if (m < b1[tk]) {
                        b2[tk] = b1[tk]; i2[tk] = i1[tk];
                        b1[tk] = m;      i1[tk] = ci;
                    } else if (m < b2[tk]) {
                        b2[tk] = m; i2[tk] = ci;
                    }
                }
            }
            nbOff = nbOffN;
            nbBase += 16;
        }

        // ---- Cross-lane top-2 merge within each 4-lane column group ----
#pragma unroll
        for (int tk = 0; tk < 4; tk++) {
#pragma unroll
            for (int off = 1; off <= 2; off <<= 1) {
                float ob1 = __shfl_xor_sync(0xFFFFFFFFu, b1[tk], off);
                int   oi1 = __shfl_xor_sync(0xFFFFFFFFu, i1[tk], off);
                float ob2 = __shfl_xor_sync(0xFFFFFFFFu, b2[tk], off);
                int   oi2 = __shfl_xor_sync(0xFFFFFFFFu, i2[tk], off);
                if (ob1 < b1[tk] || (ob1 == b1[tk] && oi1 < i1[tk])) {
                    if (b1[tk] < ob2 || (b1[tk] == ob2 && i1[tk] < oi2)) {
                        b2[tk] = b1[tk]; i2[tk] = i1[tk];
                    } else {
                        b2[tk] = ob2; i2[tk] = oi2;
                    }
                    b1[tk] = ob1; i1[tk] = oi1;
                } else if (ob1 < b2[tk] || (ob1 == b2[tk] && oi1 < i2[tk])) {
                    b2[tk] = ob1; i2[tk] = oi1;
                }
            }
        }
        if ((lane & 3) == 0) {
#pragma unroll
            for (int tk = 0; tk < 4; tk++) {
                int row = warpRow + (tk >> 1) * 16 + (tk & 1) * 8 + (lane >> 2);
                *(int2*)(smem + SMEM_IDX + row * 8) = make_int2(i1[tk], i2[tk]);
            }
        }
        __syncthreads();

        // ---- Exact fp32 rescore: one thread per row, both candidates ----
        {
            const size_t g = base + tid;
            if (g < (size_t)NROWS) {
                int2 c = *(const int2*)(smem + SMEM_IDX + tid * 8);
                int win = c.x;
                if (c.x != c.y) {
                    const float4* xr = (const float4*)(x + g * DDIM);
                    const float4* p1 = (const float4*)(emb + (size_t)c.x * DDIM);
                    const float4* p2 = (const float4*)(emb + (size_t)c.y * DDIM);
                    float d1 = 0.f, d2 = 0.f;
#pragma unroll
                    for (int j = 0; j < 16; j++) {
                        float4 xv = xr[j], a = p1[j], b = p2[j];
                        float u0 = xv.x - a.x; d1 = fmaf(u0, u0, d1);
                        float u1 = xv.y - a.y; d1 = fmaf(u1, u1, d1);
                        float u2 = xv.z - a.z; d1 = fmaf(u2, u2, d1);
                        float u3 = xv.w - a.w; d1 = fmaf(u3, u3, d1);
                        float v0 = xv.x - b.x; d2 = fmaf(v0, v0, d2);
                        float v1 = xv.y - b.y; d2 = fmaf(v1, v1, d2);
                        float v2 = xv.z - b.z; d2 = fmaf(v2, v2, d2);
                        float v3 = xv.w - b.w; d2 = fmaf(v3, v3, d2);
                    }
                    if (d2 < d1 || (d2 == d1 && c.y < c.x)) win = c.y;
                }
                ((int*)(smem + SMEM_WIN))[tid] = win;
                if (out_size >= NROWS * DDIM + NROWS) {
                    out[(size_t)NROWS * DDIM + g] = (float)win;
                }
            }
        }
        __syncthreads();

        // ---- Gather quantized rows (8 threads per row, 32B each) ----
        if (out_size >= NROWS * DDIM) {
#pragma unroll
            for (int sweep = 0; sweep < 8; sweep++) {
                int r = sweep * 64 + (tid >> 3);
                size_t gr = base + r;
                if (gr < (size_t)NROWS) {
                    int w = ((const int*)(smem + SMEM_WIN))[r];
                    const float4* e = (const float4*)(emb + (size_t)w * DDIM) + (tid & 7) * 2;
                    float4* q = (float4*)(out + gr * DDIM) + (tid & 7) * 2;
                    q[0] = e[0]; q[1] = e[1];
                }
            }
        }
        __syncthreads();   // protect IDX/WIN before next tile
    }
}

extern "C" void kernel_launch(void* const* d_in, const int* in_sizes, int n_in,
                              void* d_out, int out_size) {
    const float* x   = (const float*)d_in[0];
    const float* emb = (const float*)d_in[1];
    float* out = (float*)d_out;
    cudaFuncSetAttribute(vq_kernel, cudaFuncAttributeMaxDynamicSharedMemorySize, SMEM_TOTAL);
    vq_kernel<<<148, NTHREADS, SMEM_TOTAL>>>(x, emb, out, out_size);
}

// round 8
// speedup vs baseline: 1.0317x; 1.0317x over previous
#include <cuda_runtime.h>
#include <cuda_fp16.h>
#include <cstdint>

// Problem constants
#define NROWS   500000
#define KCODES  512
#define DDIM    64
#define TILE_M  512
#define NTHREADS 512
#define NUMTILES ((NROWS + TILE_M - 1) / TILE_M)   // 977

// Shared memory layout (byte offsets into dynamic smem)
#define SMEM_B_HI   0            // 512 x 128B fp16 (-2*e hi), SW128-swizzled
#define SMEM_B_LO   65536        // 512 x 128B fp16 (-2*e residual)
#define SMEM_ESQ    131072       // 512 floats (||e_k||^2)
#define SMEM_IDX    133120       // 512 int2 (top-2 candidates per row)
#define SMEM_WIN    137216       // 512 int  (winner per row)
#define SMEM_TOTAL  139264

__device__ __forceinline__ uint32_t smem_u32(const void* p) {
    uint32_t a;
    asm("{ .reg .u64 t; cvta.to.shared.u64 t, %1; cvt.u32.u64 %0, t; }" : "=r"(a) : "l"(p));
    return a;
}
__device__ __forceinline__ uint32_t swz(uint32_t bo) { return bo ^ ((bo >> 3) & 0x70); }

__device__ __forceinline__ void mma_f16(float* d, const uint32_t* a, const uint32_t* b) {
    asm volatile(
        "mma.sync.aligned.m16n8k16.row.col.f32.f16.f16.f32 "
        "{%0,%1,%2,%3}, {%4,%5,%6,%7}, {%8,%9}, {%0,%1,%2,%3};"
        : "+f"(d[0]), "+f"(d[1]), "+f"(d[2]), "+f"(d[3])
        : "r"(a[0]), "r"(a[1]), "r"(a[2]), "r"(a[3]), "r"(b[0]), "r"(b[1]));
}
// fp16-accumulator variant: D/C = 2 regs (4 halves), independent short chain.
__device__ __forceinline__ void mma_f16a(uint32_t* d, const uint32_t* a, const uint32_t* b) {
    asm volatile(
        "mma.sync.aligned.m16n8k16.row.col.f16.f16.f16.f16 "
        "{%0,%1}, {%2,%3,%4,%5}, {%6,%7}, {%0,%1};"
        : "+r"(d[0]), "+r"(d[1])
        : "r"(a[0]), "r"(a[1]), "r"(a[2]), "r"(a[3]), "r"(b[0]), "r"(b[1]));
}
__device__ __forceinline__ void ldsm4(uint32_t* r, uint32_t addr) {
    asm volatile("ldmatrix.sync.aligned.m8n8.x4.shared.b16 {%0,%1,%2,%3}, [%4];"
        : "=r"(r[0]), "=r"(r[1]), "=r"(r[2]), "=r"(r[3]) : "r"(addr));
}

// Split float2 into fp16 hi pair + fp16 residual pair (packed).
__device__ __forceinline__ void split2(float2 v, uint32_t& h, uint32_t& l) {
    __half2 hh = __floats2half2_rn(v.x, v.y);
    float2 hf = __half22float2(hh);
    __half2 ll = __floats2half2_rn(v.x - hf.x, v.y - hf.y);
    h = *reinterpret_cast<uint32_t*>(&hh);
    l = *reinterpret_cast<uint32_t*>(&ll);
}

// Split 8 fp32 (scaled) -> fp16 hi/lo packed uint4; accumulate squares of originals.
__device__ __forceinline__ void split8(float4 v0, float4 v1, float scale,
                                       uint4& hi, uint4& lo, float& acc) {
    float f[8] = {v0.x, v0.y, v0.z, v0.w, v1.x, v1.y, v1.z, v1.w};
    uint32_t h[4], l[4];
#pragma unroll
    for (int i = 0; i < 4; i++) {
        acc = fmaf(f[2*i], f[2*i], acc);
        acc = fmaf(f[2*i+1], f[2*i+1], acc);
        split2(make_float2(f[2*i] * scale, f[2*i+1] * scale), h[i], l[i]);
    }
    hi = make_uint4(h[0], h[1], h[2], h[3]);
    lo = make_uint4(l[0], l[1], l[2], l[3]);
}

__global__ void __launch_bounds__(NTHREADS, 1) vq_kernel(
    const float* __restrict__ x, const float* __restrict__ emb,
    float* __restrict__ out, int out_size)
{
    extern __shared__ char smem[];
    const uint32_t sb = smem_u32(smem);
    const int tid  = threadIdx.x;
    const int lane = tid & 31;
    const int warpRow = (tid >> 5) * 32;     // 16 warps x 32 rows = 512 rows

    // ---- Stage B = fp16 split of (-2 * embedding), SW128; compute e_sq ----
    {
        int r = tid;                          // 0..511
        const float4* src = (const float4*)(emb + (size_t)r * DDIM);
        float ssum = 0.f;
#pragma unroll
        for (int j = 0; j < 16; j += 2) {
            uint4 hi, lo;
            split8(src[j], src[j + 1], -2.0f, hi, lo, ssum);
            uint32_t sw = swz((uint32_t)r * 128u + (uint32_t)(j >> 1) * 16u);
            *(uint4*)(smem + SMEM_B_HI + sw) = hi;
            *(uint4*)(smem + SMEM_B_LO + sw) = lo;
        }
        ((float*)(smem + SMEM_ESQ))[r] = ssum;
    }
    __syncthreads();

    // ---- Per-lane constant B addressing (swizzle algebra hoisted) ----
    const int bRow4 = (lane & 7) + ((lane >> 4) << 3);
    const int bKb4  = ((lane >> 3) & 1) << 4;
    const uint32_t laneBaseB = (uint32_t)bRow4 * 128u + (uint32_t)(bKb4 ^ ((lane & 1) << 4));
    const uint32_t kXor = (uint32_t)(lane & 6) << 4;
    uint32_t bAddrHi[4];
#pragma unroll
    for (int ks = 0; ks < 4; ks++) {
        bAddrHi[ks] = sb + SMEM_B_HI + laneBaseB + (((uint32_t)ks * 32u) ^ kXor);
    }

    const float* esq = (const float*)(smem + SMEM_ESQ);
    const int ciB = (lane & 3) * 2;

    for (int t = blockIdx.x; t < NUMTILES; t += gridDim.x) {
        const size_t base = (size_t)t * TILE_M;

        // ---- A fragments straight from global (no smem): 2 subtiles x 4 ks ----
        uint32_t ah[2][4][4], al[2][4][4];
        {
            const int kA = (lane & 3) * 2;
#pragma unroll
            for (int s = 0; s < 2; s++) {
                size_t r0 = base + warpRow + s * 16 + (lane >> 2);
                size_t r1 = r0 + 8;
                if (r0 >= NROWS) r0 = NROWS - 1;   // clamp: garbage rows never emitted
                if (r1 >= NROWS) r1 = NROWS - 1;
                const float* p0 = x + r0 * DDIM + kA;
                const float* p1 = x + r1 * DDIM + kA;
#pragma unroll
                for (int ks = 0; ks < 4; ks++) {
                    split2(*(const float2*)(p0 + ks * 16),     ah[s][ks][0], al[s][ks][0]);
                    split2(*(const float2*)(p1 + ks * 16),     ah[s][ks][1], al[s][ks][1]);
                    split2(*(const float2*)(p0 + ks * 16 + 8), ah[s][ks][2], al[s][ks][2]);
                    split2(*(const float2*)(p1 + ks * 16 + 8), ah[s][ks][3], al[s][ks][3]);
                }
            }
        }

        // ---- Top-2 trackers: tk = s*2 + rowhalf; indices packed i1|i2<<16 ----
        float b1[4], b2[4]; uint32_t i12[4];
#pragma unroll
        for (int k = 0; k < 4; k++) { b1[k] = 3.4e38f; b2[k] = 3.4e38f; i12[k] = 0; }

        uint32_t nbOff = 0;
        int nbBase = ciB;    // nb + ciB, incremented by 16 per np

#pragma unroll 1
        for (int np = 0; np < 32; np++) {
            const int nb = np * 16;
            float2 e01 = *(const float2*)(esq + nb + ciB);
            float2 e23 = *(const float2*)(esq + nb + 8 + ciB);
            float acc[2][2][4];       // f32 chains: ah*bh + ah*bl (depth 8)
            uint32_t facc[2][2][2];   // f16 chains: al*bh (depth 4)
#pragma unroll
            for (int s = 0; s < 2; s++) {
                acc[s][0][0] = e01.x; acc[s][0][1] = e01.y;
                acc[s][0][2] = e01.x; acc[s][0][3] = e01.y;
                acc[s][1][0] = e23.x; acc[s][1][1] = e23.y;
                acc[s][1][2] = e23.x; acc[s][1][3] = e23.y;
                facc[s][0][0] = 0u; facc[s][0][1] = 0u;
                facc[s][1][0] = 0u; facc[s][1][1] = 0u;
            }

#pragma unroll
            for (int ks = 0; ks < 4; ks++) {
                uint32_t bh[4], bl[4];
                ldsm4(bh, bAddrHi[ks] + nbOff);
                // f32 chains (hi pass) + f16 chains (lo-A pass) on bh
                mma_f16(acc[0][0], ah[0][ks], bh);
                mma_f16(acc[0][1], ah[0][ks], bh + 2);
                mma_f16(acc[1][0], ah[1][ks], bh);
                mma_f16(acc[1][1], ah[1][ks], bh + 2);
                mma_f16a(facc[0][0], al[0][ks], bh);
                mma_f16a(facc[0][1], al[0][ks], bh + 2);
                mma_f16a(facc[1][0], al[1][ks], bh);
                mma_f16a(facc[1][1], al[1][ks], bh + 2);
                // f32 chains (lo-B pass)
                ldsm4(bl, bAddrHi[ks] + nbOff + 65536u);
                mma_f16(acc[0][0], ah[0][ks], bl);
                mma_f16(acc[0][1], ah[0][ks], bl + 2);
                mma_f16(acc[1][0], ah[1][ks], bl);
                mma_f16(acc[1][1], ah[1][ks], bl + 2);
                // al x bl dropped: ~1e-7 per product; exact rescore covers it
            }

            // ---- Epilogue: fold f16 chains, pre-min tree, ONE top-2 update/tk ----
#pragma unroll
            for (int s = 0; s < 2; s++) {
#pragma unroll
                for (int nt = 0; nt < 2; nt++) {
                    float2 f0 = __half22float2(*(const __half2*)&facc[s][nt][0]);
                    float2 f1 = __half22float2(*(const __half2*)&facc[s][nt][1]);
                    acc[s][nt][0] += f0.x; acc[s][nt][1] += f0.y;
                    acc[s][nt][2] += f1.x; acc[s][nt][3] += f1.y;
                }
#pragma unroll
                for (int h = 0; h < 2; h++) {
                    const int tk = s * 2 + h;
                    float s00 = acc[s][0][h*2], s01 = acc[s][0][h*2+1];
                    float s10 = acc[s][1][h*2], s11 = acc[s][1][h*2+1];
                    float m0 = fminf(s00, s01); int o0 = (s01 < s00) ? 1 : 0;
                    float m1 = fminf(s10, s11); int o1 = (s11 < s10) ? 9 : 8;
                    float m  = fminf(m0, m1);   int off = (m1 < m0) ? o1 : o0;
                    uint32_t ci = (uint32_t)(nbBase + off);
                    if (m < b1[tk]) {
                        b2[tk] = b1[tk];
                        i12[tk] = (i12[tk] << 16) | ci;
                        b1[tk] = m;
                    } else if (m < b2[tk]) {
                        b2[tk] = m;
                        i12[tk] = (i12[tk] & 0xFFFFu) | (ci << 16);
                    }
                }
            }
            nbOff += 2048;
            nbBase += 16;
        }

        // ---- Cross-lane top-2 merge within each 4-lane column group ----
#pragma unroll
        for (int tk = 0; tk < 4; tk++) {
            int i1 = (int)(i12[tk] & 0xFFFFu);
            int i2 = (int)(i12[tk] >> 16);
            float v1 = b1[tk], v2 = b2[tk];
#pragma unroll
            for (int off = 1; off <= 2; off <<= 1) {
                float ob1 = __shfl_xor_sync(0xFFFFFFFFu, v1, off);
                float ob2 = __shfl_xor_sync(0xFFFFFFFFu, v2, off);
                uint32_t oi = __shfl_xor_sync(0xFFFFFFFFu, (uint32_t)i1 | ((uint32_t)i2 << 16), off);
                int oi1 = (int)(oi & 0xFFFFu), oi2 = (int)(oi >> 16);
                if (ob1 < v1 || (ob1 == v1 && oi1 < i1)) {
                    if (v1 < ob2 || (v1 == ob2 && i1 < oi2)) { v2 = v1; i2 = i1; }
                    else                                     { v2 = ob2; i2 = oi2; }
                    v1 = ob1; i1 = oi1;
                } else if (ob1 < v2 || (ob1 == v2 && oi1 < i2)) {
                    v2 = ob1; i2 = oi1;
                }
            }
            if ((lane & 3) == 0) {
                int row = warpRow + (tk >> 1) * 16 + (tk & 1) * 8 + (lane >> 2);
                *(int2*)(smem + SMEM_IDX + row * 8) = make_int2(i1, i2);
            }
        }
        __syncthreads();

        // ---- Exact fp32 rescore: one thread per row, both candidates ----
        {
            const size_t g = base + tid;
            if (g < (size_t)NROWS) {
                int2 c = *(const int2*)(smem + SMEM_IDX + tid * 8);
                int win = c.x;
                if (c.x != c.y) {
                    const float4* xr = (const float4*)(x + g * DDIM);
                    const float4* p1 = (const float4*)(emb + (size_t)c.x * DDIM);
                    const float4* p2 = (const float4*)(emb + (size_t)c.y * DDIM);
                    float d1 = 0.f, d2 = 0.f;
#pragma unroll
                    for (int j = 0; j < 16; j++) {
                        float4 xv = xr[j], a = p1[j], b = p2[j];
                        float u0 = xv.x - a.x; d1 = fmaf(u0, u0, d1);
                        float u1 = xv.y - a.y; d1 = fmaf(u1, u1, d1);
                        float u2 = xv.z - a.z; d1 = fmaf(u2, u2, d1);
                        float u3 = xv.w - a.w; d1 = fmaf(u3, u3, d1);
                        float v0 = xv.x - b.x; d2 = fmaf(v0, v0, d2);
                        float v1 = xv.y - b.y; d2 = fmaf(v1, v1, d2);
                        float v2 = xv.z - b.z; d2 = fmaf(v2, v2, d2);
                        float v3 = xv.w - b.w; d2 = fmaf(v3, v3, d2);
                    }
                    if (d2 < d1 || (d2 == d1 && c.y < c.x)) win = c.y;
                }
                ((int*)(smem + SMEM_WIN))[tid] = win;
                if (out_size >= NROWS * DDIM + NROWS) {
                    out[(size_t)NROWS * DDIM + g] = (float)win;
                }
            }
        }
        __syncthreads();

        // ---- Gather quantized rows (8 threads per row, 32B each) ----
        if (out_size >= NROWS * DDIM) {
#pragma unroll
            for (int sweep = 0; sweep < 8; sweep++) {
                int r = sweep * 64 + (tid >> 3);
                size_t gr = base + r;
                if (gr < (size_t)NROWS) {
                    int w = ((const int*)(smem + SMEM_WIN))[r];
                    const float4* e = (const float4*)(emb + (size_t)w * DDIM) + (tid & 7) * 2;
                    float4* q = (float4*)(out + gr * DDIM) + (tid & 7) * 2;
                    q[0] = e[0]; q[1] = e[1];
                }
            }
        }
        __syncthreads();   // protect IDX/WIN before next tile
    }
}

extern "C" void kernel_launch(void* const* d_in, const int* in_sizes, int n_in,
                              void* d_out, int out_size) {
    const float* x   = (const float*)d_in[0];
    const float* emb = (const float*)d_in[1];
    float* out = (float*)d_out;
    cudaFuncSetAttribute(vq_kernel, cudaFuncAttributeMaxDynamicSharedMemorySize, SMEM_TOTAL);
    vq_kernel<<<148, NTHREADS, SMEM_TOTAL>>>(x, emb, out, out_size);
}

// round 9
// speedup vs baseline: 1.0864x; 1.0530x over previous
#include <cuda_runtime.h>
#include <cuda_fp16.h>
#include <cstdint>

// Problem constants
#define NROWS   500000
#define KCODES  512
#define DDIM    64
#define TILE_M  384
#define NTHREADS 768
#define NUMTILES ((NROWS + TILE_M - 1) / TILE_M)   // 1303

// Shared memory layout (byte offsets into dynamic smem)
#define SMEM_B_HI   0            // 512 x 128B fp16 (-2*e hi), SW128-swizzled
#define SMEM_B_LO   65536        // 512 x 128B fp16 (-2*e residual)
#define SMEM_ESQ    131072       // 512 floats (||e_k||^2)
#define SMEM_IDX    133120       // 384 int2 (top-2 candidates per row)
#define SMEM_WIN    137216       // 384 int  (winner per row)
#define SMEM_TOTAL  139264

__device__ __forceinline__ uint32_t smem_u32(const void* p) {
    uint32_t a;
    asm("{ .reg .u64 t; cvta.to.shared.u64 t, %1; cvt.u32.u64 %0, t; }" : "=r"(a) : "l"(p));
    return a;
}
__device__ __forceinline__ uint32_t swz(uint32_t bo) { return bo ^ ((bo >> 3) & 0x70); }

__device__ __forceinline__ void mma_f16(float* d, const uint32_t* a, const uint32_t* b) {
    asm volatile(
        "mma.sync.aligned.m16n8k16.row.col.f32.f16.f16.f32 "
        "{%0,%1,%2,%3}, {%4,%5,%6,%7}, {%8,%9}, {%0,%1,%2,%3};"
        : "+f"(d[0]), "+f"(d[1]), "+f"(d[2]), "+f"(d[3])
        : "r"(a[0]), "r"(a[1]), "r"(a[2]), "r"(a[3]), "r"(b[0]), "r"(b[1]));
}
__device__ __forceinline__ void ldsm4(uint32_t* r, uint32_t addr) {
    asm volatile("ldmatrix.sync.aligned.m8n8.x4.shared.b16 {%0,%1,%2,%3}, [%4];"
        : "=r"(r[0]), "=r"(r[1]), "=r"(r[2]), "=r"(r[3]) : "r"(addr));
}

// Split float2 into fp16 hi pair + fp16 residual pair (packed).
__device__ __forceinline__ void split2(float2 v, uint32_t& h, uint32_t& l) {
    __half2 hh = __floats2half2_rn(v.x, v.y);
    float2 hf = __half22float2(hh);
    __half2 ll = __floats2half2_rn(v.x - hf.x, v.y - hf.y);
    h = *reinterpret_cast<uint32_t*>(&hh);
    l = *reinterpret_cast<uint32_t*>(&ll);
}

// Split 8 fp32 (scaled) -> fp16 hi/lo packed uint4; accumulate squares of originals.
__device__ __forceinline__ void split8(float4 v0, float4 v1, float scale,
                                       uint4& hi, uint4& lo, float& acc) {
    float f[8] = {v0.x, v0.y, v0.z, v0.w, v1.x, v1.y, v1.z, v1.w};
    uint32_t h[4], l[4];
#pragma unroll
    for (int i = 0; i < 4; i++) {
        acc = fmaf(f[2*i], f[2*i], acc);
        acc = fmaf(f[2*i+1], f[2*i+1], acc);
        split2(make_float2(f[2*i] * scale, f[2*i+1] * scale), h[i], l[i]);
    }
    hi = make_uint4(h[0], h[1], h[2], h[3]);
    lo = make_uint4(l[0], l[1], l[2], l[3]);
}

__global__ void __launch_bounds__(NTHREADS, 1) vq_kernel(
    const float* __restrict__ x, const float* __restrict__ emb,
    float* __restrict__ out, int out_size)
{
    extern __shared__ char smem[];
    const uint32_t sb = smem_u32(smem);
    const int tid  = threadIdx.x;
    const int lane = tid & 31;
    const int warpRow = (tid >> 5) * 16;     // 24 warps x 16 rows = 384 rows

    // ---- Stage B = fp16 split of (-2 * embedding), SW128; compute e_sq ----
    if (tid < 512) {
        int r = tid;
        const float4* src = (const float4*)(emb + (size_t)r * DDIM);
        float ssum = 0.f;
#pragma unroll
        for (int j = 0; j < 16; j += 2) {
            uint4 hi, lo;
            split8(src[j], src[j + 1], -2.0f, hi, lo, ssum);
            uint32_t sw = swz((uint32_t)r * 128u + (uint32_t)(j >> 1) * 16u);
            *(uint4*)(smem + SMEM_B_HI + sw) = hi;
            *(uint4*)(smem + SMEM_B_LO + sw) = lo;
        }
        ((float*)(smem + SMEM_ESQ))[r] = ssum;
    }
    __syncthreads();

    // ---- Per-lane constant B addressing (swizzle algebra hoisted) ----
    const int bRow4 = (lane & 7) + ((lane >> 4) << 3);
    const int bKb4  = ((lane >> 3) & 1) << 4;
    const uint32_t laneBaseB = (uint32_t)bRow4 * 128u + (uint32_t)(bKb4 ^ ((lane & 1) << 4));
    const uint32_t kXor = (uint32_t)(lane & 6) << 4;
    uint32_t bAddrHi[4];
#pragma unroll
    for (int ks = 0; ks < 4; ks++) {
        bAddrHi[ks] = sb + SMEM_B_HI + laneBaseB + (((uint32_t)ks * 32u) ^ kXor);
    }

    const float* esq = (const float*)(smem + SMEM_ESQ);
    const int ciB = (lane & 3) * 2;

    for (int t = blockIdx.x; t < NUMTILES; t += gridDim.x) {
        const size_t base = (size_t)t * TILE_M;

        // ---- A fragments straight from global (no smem): 1 subtile x 4 ks ----
        uint32_t ah[4][4], al[4][4];
        {
            const int kA = (lane & 3) * 2;
            size_t r0 = base + warpRow + (lane >> 2);
            size_t r1 = r0 + 8;
            if (r0 >= NROWS) r0 = NROWS - 1;   // clamp: garbage rows never emitted
            if (r1 >= NROWS) r1 = NROWS - 1;
            const float* p0 = x + r0 * DDIM + kA;
            const float* p1 = x + r1 * DDIM + kA;
#pragma unroll
            for (int ks = 0; ks < 4; ks++) {
                split2(*(const float2*)(p0 + ks * 16),     ah[ks][0], al[ks][0]);
                split2(*(const float2*)(p1 + ks * 16),     ah[ks][1], al[ks][1]);
                split2(*(const float2*)(p0 + ks * 16 + 8), ah[ks][2], al[ks][2]);
                split2(*(const float2*)(p1 + ks * 16 + 8), ah[ks][3], al[ks][3]);
            }
        }

        // ---- Top-2 trackers: tk = rowhalf (row r, row r+8); packed indices ----
        float b1[2], b2[2]; uint32_t i12[2];
#pragma unroll
        for (int k = 0; k < 2; k++) { b1[k] = 3.4e38f; b2[k] = 3.4e38f; i12[k] = 0; }

        uint32_t nbOff = 0;
        int nbBase = ciB;    // nb + ciB, incremented by 16 per np

#pragma unroll 1
        for (int np = 0; np < 32; np++) {
            const int nb = np * 16;
            float2 e01 = *(const float2*)(esq + nb + ciB);
            float2 e23 = *(const float2*)(esq + nb + 8 + ciB);
            float acc[2][4];     // [nt][reg]
            acc[0][0] = e01.x; acc[0][1] = e01.y; acc[0][2] = e01.x; acc[0][3] = e01.y;
            acc[1][0] = e23.x; acc[1][1] = e23.y; acc[1][2] = e23.x; acc[1][3] = e23.y;

#pragma unroll
            for (int ks = 0; ks < 4; ks++) {
                uint32_t bh[4], bl[4];
                ldsm4(bh, bAddrHi[ks] + nbOff);
                ldsm4(bl, bAddrHi[ks] + nbOff + 65536u);
                mma_f16(acc[0], ah[ks], bh);
                mma_f16(acc[1], ah[ks], bh + 2);
                mma_f16(acc[0], al[ks], bh);
                mma_f16(acc[1], al[ks], bh + 2);
                mma_f16(acc[0], ah[ks], bl);
                mma_f16(acc[1], ah[ks], bl + 2);
                // al x bl dropped: ~1e-7 per product; exact rescore covers it
            }

            // ---- Epilogue: pre-min tree (off-chain), ONE top-2 update per tk ----
#pragma unroll
            for (int h = 0; h < 2; h++) {
                float s00 = acc[0][h*2], s01 = acc[0][h*2+1];
                float s10 = acc[1][h*2], s11 = acc[1][h*2+1];
                float m0 = fminf(s00, s01); int o0 = (s01 < s00) ? 1 : 0;
                float m1 = fminf(s10, s11); int o1 = (s11 < s10) ? 9 : 8;
                float m  = fminf(m0, m1);   int off = (m1 < m0) ? o1 : o0;
                uint32_t ci = (uint32_t)(nbBase + off);
                if (m < b1[h]) {
                    b2[h] = b1[h];
                    i12[h] = (i12[h] << 16) | ci;
                    b1[h] = m;
                } else if (m < b2[h]) {
                    b2[h] = m;
                    i12[h] = (i12[h] & 0xFFFFu) | (ci << 16);
                }
            }
            nbOff += 2048;
            nbBase += 16;
        }

        // ---- Cross-lane top-2 merge within each 4-lane column group ----
#pragma unroll
        for (int tk = 0; tk < 2; tk++) {
            int i1 = (int)(i12[tk] & 0xFFFFu);
            int i2 = (int)(i12[tk] >> 16);
            float v1 = b1[tk], v2 = b2[tk];
#pragma unroll
            for (int off = 1; off <= 2; off <<= 1) {
                float ob1 = __shfl_xor_sync(0xFFFFFFFFu, v1, off);
                float ob2 = __shfl_xor_sync(0xFFFFFFFFu, v2, off);
                uint32_t oi = __shfl_xor_sync(0xFFFFFFFFu, (uint32_t)i1 | ((uint32_t)i2 << 16), off);
                int oi1 = (int)(oi & 0xFFFFu), oi2 = (int)(oi >> 16);
                if (ob1 < v1 || (ob1 == v1 && oi1 < i1)) {
                    if (v1 < ob2 || (v1 == ob2 && i1 < oi2)) { v2 = v1; i2 = i1; }
                    else                                     { v2 = ob2; i2 = oi2; }
                    v1 = ob1; i1 = oi1;
                } else if (ob1 < v2 || (ob1 == v2 && oi1 < i2)) {
                    v2 = ob1; i2 = oi1;
                }
            }
            if ((lane & 3) == 0) {
                int row = warpRow + tk * 8 + (lane >> 2);
                *(int2*)(smem + SMEM_IDX + row * 8) = make_int2(i1, i2);
            }
        }
        __syncthreads();

        // ---- Exact fp32 rescore: one thread per row, both candidates ----
        if (tid < TILE_M) {
            const size_t g = base + tid;
            if (g < (size_t)NROWS) {
                int2 c = *(const int2*)(smem + SMEM_IDX + tid * 8);
                int win = c.x;
                if (c.x != c.y) {
                    const float4* xr = (const float4*)(x + g * DDIM);
                    const float4* p1 = (const float4*)(emb + (size_t)c.x * DDIM);
                    const float4* p2 = (const float4*)(emb + (size_t)c.y * DDIM);
                    float d1 = 0.f, d2 = 0.f;
#pragma unroll
                    for (int j = 0; j < 16; j++) {
                        float4 xv = xr[j], a = p1[j], b = p2[j];
                        float u0 = xv.x - a.x; d1 = fmaf(u0, u0, d1);
                        float u1 = xv.y - a.y; d1 = fmaf(u1, u1, d1);
                        float u2 = xv.z - a.z; d1 = fmaf(u2, u2, d1);
                        float u3 = xv.w - a.w; d1 = fmaf(u3, u3, d1);
                        float v0 = xv.x - b.x; d2 = fmaf(v0, v0, d2);
                        float v1 = xv.y - b.y; d2 = fmaf(v1, v1, d2);
                        float v2 = xv.z - b.z; d2 = fmaf(v2, v2, d2);
                        float v3 = xv.w - b.w; d2 = fmaf(v3, v3, d2);
                    }
                    if (d2 < d1 || (d2 == d1 && c.y < c.x)) win = c.y;
                }
                ((int*)(smem + SMEM_WIN))[tid] = win;
                if (out_size >= NROWS * DDIM + NROWS) {
                    out[(size_t)NROWS * DDIM + g] = (float)win;
                }
            }
        }
        __syncthreads();

        // ---- Gather quantized rows (8 threads per row, 32B each) ----
        if (out_size >= NROWS * DDIM) {
#pragma unroll
            for (int sweep = 0; sweep < 4; sweep++) {
                int r = sweep * 96 + (tid >> 3);
                size_t gr = base + r;
                if (r < TILE_M && gr < (size_t)NROWS) {
                    int w = ((const int*)(smem + SMEM_WIN))[r];
                    const float4* e = (const float4*)(emb + (size_t)w * DDIM) + (tid & 7) * 2;
                    float4* q = (float4*)(out + gr * DDIM) + (tid & 7) * 2;
                    q[0] = e[0]; q[1] = e[1];
                }
            }
        }
        __syncthreads();   // protect IDX/WIN before next tile
    }
}

extern "C" void kernel_launch(void* const* d_in, const int* in_sizes, int n_in,
                              void* d_out, int out_size) {
    const float* x   = (const float*)d_in[0];
    const float* emb = (const float*)d_in[1];
    float* out = (float*)d_out;
    cudaFuncSetAttribute(vq_kernel, cudaFuncAttributeMaxDynamicSharedMemorySize, SMEM_TOTAL);
    vq_kernel<<<148, NTHREADS, SMEM_TOTAL>>>(x, emb, out, out_size);
}